// round 1
// baseline (speedup 1.0000x reference)
#include <cuda_runtime.h>
#include <cuda_bf16.h>

// ---------------------------------------------------------------------------
// LightweightSelfAttention  (B=2, C=512, H=W=64, heads=8, dh=64)
// Stages:
//   1) depthwise 3x3 conv (pad 1)          x -> g_y
//   2) qkv 1x1 conv  = GEMM 1536x512 @ 512x4096 (per batch)   g_y -> g_qkv
//   3) flash attention per (b, head)       g_qkv -> g_o
//   4) proj 1x1 conv = GEMM 512x512 @ 512x4096 + bias         g_o -> d_out
// All fp32; inner loops use packed fma.rn.f32x2 (full-rate FMA on sm_103a).
// ---------------------------------------------------------------------------

#define BATCH 2
#define CDIM 512
#define HEADS 8
#define DH 64
#define NPIX 4096            // 64*64
#define TOTAL (BATCH*CDIM*NPIX)

// scratch (module-load allocated, not counted as runtime allocs)
__device__ float g_y[BATCH * CDIM * NPIX];          // 16 MB
__device__ float g_qkv[BATCH * 3 * CDIM * NPIX];    // 48 MB
__device__ float g_o[BATCH * CDIM * NPIX];          // 16 MB

// ---------------- f32x2 helpers -------------------------------------------
__device__ __forceinline__ unsigned long long pk2(float lo, float hi) {
    unsigned long long r;
    asm("mov.b64 %0, {%1, %2};" : "=l"(r)
        : "r"(__float_as_uint(lo)), "r"(__float_as_uint(hi)));
    return r;
}
__device__ __forceinline__ void upk2(unsigned long long v, float& lo, float& hi) {
    unsigned int a, b;
    asm("mov.b64 {%0, %1}, %2;" : "=r"(a), "=r"(b) : "l"(v));
    lo = __uint_as_float(a); hi = __uint_as_float(b);
}
__device__ __forceinline__ unsigned long long fma2(unsigned long long a,
                                                   unsigned long long b,
                                                   unsigned long long c) {
    unsigned long long d;
    asm("fma.rn.f32x2 %0, %1, %2, %3;" : "=l"(d) : "l"(a), "l"(b), "l"(c));
    return d;
}
__device__ __forceinline__ unsigned long long mul2(unsigned long long a,
                                                   unsigned long long b) {
    unsigned long long d;
    asm("mul.rn.f32x2 %0, %1, %2;" : "=l"(d) : "l"(a), "l"(b));
    return d;
}

// ---------------- 1) depthwise 3x3 ----------------------------------------
__global__ void k_dwconv(const float* __restrict__ x,
                         const float* __restrict__ w,
                         float* __restrict__ y) {
    int idx = blockIdx.x * blockDim.x + threadIdx.x;
    if (idx >= TOTAL) return;
    int n = idx & (NPIX - 1);
    int c = (idx >> 12) & (CDIM - 1);
    int hh = n >> 6, ww = n & 63;
    const float* xb = x + (long long)(idx >> 12) * NPIX;  // (b*C+c) plane
    const float* wc = w + c * 9;
    float s = 0.f;
#pragma unroll
    for (int i = 0; i < 3; i++) {
        int h2 = hh + i - 1;
        if ((unsigned)h2 < 64u) {
#pragma unroll
            for (int j = 0; j < 3; j++) {
                int w2 = ww + j - 1;
                if ((unsigned)w2 < 64u) s += xb[h2 * 64 + w2] * wc[i * 3 + j];
            }
        }
    }
    y[idx] = s;
}

// ---------------- 2/4) GEMM: C[M,N] = A[M,K] @ B[K,N] (+bias) -------------
// 64x64 tile, 16-deep k tiles, 4x4 micro per thread, 256 threads.
__global__ __launch_bounds__(256) void k_gemm64(
    const float* __restrict__ A, const float* __restrict__ B,
    float* __restrict__ C, const float* __restrict__ bias,
    int M, int N, int K, long long sB, long long sC) {
    __shared__ float As[16 * 68];
    __shared__ float Bs[16 * 64];
    int tid = threadIdx.x;
    int ty = tid >> 4, tx = tid & 15;
    int m0 = blockIdx.y * 64, n0 = blockIdx.x * 64;
    const float* Bb = B + (long long)blockIdx.z * sB;
    float* Cb = C + (long long)blockIdx.z * sC;

    unsigned long long acc[4][2];
#pragma unroll
    for (int i = 0; i < 4; i++) { acc[i][0] = 0ull; acc[i][1] = 0ull; }

    for (int k0 = 0; k0 < K; k0 += 16) {
#pragma unroll
        for (int l = 0; l < 4; l++) {
            int idx = tid + l * 256;
            int m = idx >> 4, kk = idx & 15;
            As[kk * 68 + m] = A[(long long)(m0 + m) * K + k0 + kk];
            int kb = idx >> 6, nn = idx & 63;
            Bs[kb * 64 + nn] = Bb[(long long)(k0 + kb) * N + n0 + nn];
        }
        __syncthreads();
#pragma unroll
        for (int kk = 0; kk < 16; kk++) {
            float4 a4 = *(const float4*)&As[kk * 68 + ty * 4];
            float4 b4 = *(const float4*)&Bs[kk * 64 + tx * 4];
            unsigned long long b0 = pk2(b4.x, b4.y);
            unsigned long long b1 = pk2(b4.z, b4.w);
            float av[4] = {a4.x, a4.y, a4.z, a4.w};
#pragma unroll
            for (int i = 0; i < 4; i++) {
                unsigned long long ap = pk2(av[i], av[i]);
                acc[i][0] = fma2(ap, b0, acc[i][0]);
                acc[i][1] = fma2(ap, b1, acc[i][1]);
            }
        }
        __syncthreads();
    }
#pragma unroll
    for (int i = 0; i < 4; i++) {
        float c0, c1, c2, c3;
        upk2(acc[i][0], c0, c1);
        upk2(acc[i][1], c2, c3);
        float bv = bias ? bias[m0 + ty * 4 + i] : 0.f;
        float4 o = make_float4(c0 + bv, c1 + bv, c2 + bv, c3 + bv);
        *(float4*)&Cb[(long long)(m0 + ty * 4 + i) * N + n0 + tx * 4] = o;
    }
}

// ---------------- 3) flash attention ---------------------------------------
// One CTA = (b, head, 64-query tile). q/k/v stored (dh, N) in g_qkv.
// Smem: Qs[64*64], Ks[64*64], Vs[64*68] (transposed c-major), Ps[64*66].
#define ATTN_SMEM_FLOATS (64 * 64 + 64 * 64 + 64 * 68 + 64 * 66)
#define ATTN_SMEM_BYTES (ATTN_SMEM_FLOATS * 4)

__global__ __launch_bounds__(256, 2) void k_attn(const float* __restrict__ qkv,
                                                 float* __restrict__ o) {
    extern __shared__ float sm[];
    float* Qs = sm;                 // [d*64 + r]
    float* Ks = Qs + 64 * 64;       // [d*64 + c]
    float* Vs = Ks + 64 * 64;       // [c*68 + d]
    float* Ps = Vs + 64 * 68;       // [r*66 + c]  (also reused for O^T)

    int tid = threadIdx.x;
    int ty = tid >> 4, tx = tid & 15;
    int n0 = blockIdx.x * 64;
    int h = blockIdx.y, b = blockIdx.z;

    const float* qptr = qkv + ((long long)((b * 3 + 0) * CDIM + h * DH)) * NPIX + n0;
    const float* kptr = qkv + ((long long)((b * 3 + 1) * CDIM + h * DH)) * NPIX;
    const float* vptr = qkv + ((long long)((b * 3 + 2) * CDIM + h * DH)) * NPIX;

    // load Q tile (scaled by dh^-0.5 = 0.125)
#pragma unroll
    for (int l = 0; l < 16; l++) {
        int idx = tid + l * 256;
        int d = idx >> 6, r = idx & 63;
        Qs[d * 64 + r] = qptr[(long long)d * NPIX + r] * 0.125f;
    }

    float m_run[4], l_run[4];
    unsigned long long acc[4][2];
#pragma unroll
    for (int i = 0; i < 4; i++) {
        m_run[i] = -1e30f; l_run[i] = 0.f; acc[i][0] = 0ull; acc[i][1] = 0ull;
    }

    for (int m0 = 0; m0 < NPIX; m0 += 64) {
        __syncthreads();   // previous AV done (Vs/Ps free); Q store visible
#pragma unroll
        for (int l = 0; l < 16; l++) {
            int idx = tid + l * 256;
            int d = idx >> 6, c = idx & 63;
            Ks[d * 64 + c] = kptr[(long long)d * NPIX + m0 + c];
            Vs[c * 68 + d] = vptr[(long long)d * NPIX + m0 + c];
        }
        __syncthreads();

        // S = (scaled Q)^T K : 64x64, 4x4 per thread
        unsigned long long s2[4][2];
#pragma unroll
        for (int i = 0; i < 4; i++) { s2[i][0] = 0ull; s2[i][1] = 0ull; }
#pragma unroll 8
        for (int d = 0; d < 64; d++) {
            float4 a4 = *(const float4*)&Qs[d * 64 + ty * 4];
            float4 b4 = *(const float4*)&Ks[d * 64 + tx * 4];
            unsigned long long b0 = pk2(b4.x, b4.y);
            unsigned long long b1 = pk2(b4.z, b4.w);
            float av[4] = {a4.x, a4.y, a4.z, a4.w};
#pragma unroll
            for (int i = 0; i < 4; i++) {
                unsigned long long ap = pk2(av[i], av[i]);
                s2[i][0] = fma2(ap, b0, s2[i][0]);
                s2[i][1] = fma2(ap, b1, s2[i][1]);
            }
        }

        // online softmax
#pragma unroll
        for (int i = 0; i < 4; i++) {
            float s0, s1, s2f, s3;
            upk2(s2[i][0], s0, s1);
            upk2(s2[i][1], s2f, s3);
            float tm = fmaxf(fmaxf(s0, s1), fmaxf(s2f, s3));
            tm = fmaxf(tm, __shfl_xor_sync(0xffffffffu, tm, 1));
            tm = fmaxf(tm, __shfl_xor_sync(0xffffffffu, tm, 2));
            tm = fmaxf(tm, __shfl_xor_sync(0xffffffffu, tm, 4));
            tm = fmaxf(tm, __shfl_xor_sync(0xffffffffu, tm, 8));
            float mn = fmaxf(m_run[i], tm);
            float f = __expf(m_run[i] - mn);
            float p0 = __expf(s0 - mn);
            float p1 = __expf(s1 - mn);
            float p2 = __expf(s2f - mn);
            float p3 = __expf(s3 - mn);
            float rs = (p0 + p1) + (p2 + p3);
            rs += __shfl_xor_sync(0xffffffffu, rs, 1);
            rs += __shfl_xor_sync(0xffffffffu, rs, 2);
            rs += __shfl_xor_sync(0xffffffffu, rs, 4);
            rs += __shfl_xor_sync(0xffffffffu, rs, 8);
            l_run[i] = l_run[i] * f + rs;
            m_run[i] = mn;
            unsigned long long fp = pk2(f, f);
            acc[i][0] = mul2(acc[i][0], fp);
            acc[i][1] = mul2(acc[i][1], fp);
            int r = ty * 4 + i;
            Ps[r * 66 + tx * 4 + 0] = p0;
            Ps[r * 66 + tx * 4 + 1] = p1;
            Ps[r * 66 + tx * 4 + 2] = p2;
            Ps[r * 66 + tx * 4 + 3] = p3;
        }
        __syncthreads();

        // O += P @ V^T  (acc[r][d], loop over keys c)
#pragma unroll 4
        for (int c = 0; c < 64; c += 2) {
            float4 va = *(const float4*)&Vs[c * 68 + tx * 4];
            float4 vb = *(const float4*)&Vs[(c + 1) * 68 + tx * 4];
            unsigned long long va0 = pk2(va.x, va.y);
            unsigned long long va1 = pk2(va.z, va.w);
            unsigned long long vb0 = pk2(vb.x, vb.y);
            unsigned long long vb1 = pk2(vb.z, vb.w);
#pragma unroll
            for (int i = 0; i < 4; i++) {
                float2 pr = *(const float2*)&Ps[(ty * 4 + i) * 66 + c];
                unsigned long long pa = pk2(pr.x, pr.x);
                unsigned long long pb = pk2(pr.y, pr.y);
                acc[i][0] = fma2(pa, va0, acc[i][0]);
                acc[i][1] = fma2(pa, va1, acc[i][1]);
                acc[i][0] = fma2(pb, vb0, acc[i][0]);
                acc[i][1] = fma2(pb, vb1, acc[i][1]);
            }
        }
    }
    __syncthreads();

    // epilogue: O^T into Ps as [d*66 + r], then coalesced store
#pragma unroll
    for (int i = 0; i < 4; i++) {
        float inv = 1.0f / l_run[i];
        float c0, c1, c2, c3;
        upk2(acc[i][0], c0, c1);
        upk2(acc[i][1], c2, c3);
        int r = ty * 4 + i;
        Ps[(tx * 4 + 0) * 66 + r] = c0 * inv;
        Ps[(tx * 4 + 1) * 66 + r] = c1 * inv;
        Ps[(tx * 4 + 2) * 66 + r] = c2 * inv;
        Ps[(tx * 4 + 3) * 66 + r] = c3 * inv;
    }
    __syncthreads();

    float* optr = o + ((long long)(b * CDIM + h * DH)) * NPIX + n0;
#pragma unroll
    for (int l = 0; l < 16; l++) {
        int idx = tid + l * 256;
        int d = idx >> 6, r = idx & 63;
        optr[(long long)d * NPIX + r] = Ps[d * 66 + r];
    }
}

// ---------------------------------------------------------------------------
extern "C" void kernel_launch(void* const* d_in, const int* in_sizes, int n_in,
                              void* d_out, int out_size) {
    const float* x      = (const float*)d_in[0];
    const float* dw_w   = (const float*)d_in[1];
    const float* qkv_w  = (const float*)d_in[2];
    const float* proj_w = (const float*)d_in[3];
    const float* proj_b = (const float*)d_in[4];
    float* out = (float*)d_out;

    float *py, *pqkv, *po;
    cudaGetSymbolAddress((void**)&py,   g_y);
    cudaGetSymbolAddress((void**)&pqkv, g_qkv);
    cudaGetSymbolAddress((void**)&po,   g_o);

    cudaFuncSetAttribute(k_attn, cudaFuncAttributeMaxDynamicSharedMemorySize,
                         ATTN_SMEM_BYTES);

    // 1) depthwise conv
    k_dwconv<<<(TOTAL + 255) / 256, 256>>>(x, dw_w, py);

    // 2) qkv GEMM: (1536x512) @ (512x4096), per batch
    {
        dim3 grid(NPIX / 64, (3 * CDIM) / 64, BATCH);
        k_gemm64<<<grid, 256>>>(qkv_w, py, pqkv, nullptr,
                                3 * CDIM, NPIX, CDIM,
                                (long long)CDIM * NPIX,
                                (long long)3 * CDIM * NPIX);
    }

    // 3) attention
    {
        dim3 grid(NPIX / 64, HEADS, BATCH);
        k_attn<<<grid, 256, ATTN_SMEM_BYTES>>>(pqkv, po);
    }

    // 4) proj GEMM + bias: (512x512) @ (512x4096)
    {
        dim3 grid(NPIX / 64, CDIM / 64, BATCH);
        k_gemm64<<<grid, 256>>>(proj_w, po, out, proj_b,
                                CDIM, NPIX, CDIM,
                                (long long)CDIM * NPIX,
                                (long long)CDIM * NPIX);
    }
}

// round 4
// speedup vs baseline: 3.1085x; 3.1085x over previous
#include <cuda_runtime.h>
#include <cuda_bf16.h>
#include <cstdint>

// ---------------------------------------------------------------------------
// LightweightSelfAttention  (B=2, C=512, H=W=64, heads=8, dh=64)
//   1) depthwise 3x3 conv (pad 1)                    x -> g_y
//   2) transpose qkv_w[0:1024] -> g_wT [512][1024]
//   3) qk GEMM (transposed out): qkvt[n, 1024]       g_y -> g_qkvt
//   4) V GEMM (standard layout = V^T per head)       g_y -> g_vt [c][n]
//   5) tcgen05 attention (all-SS, K-major SW128)     -> g_ot [n, 512]
//   6) transpose ot -> [c][n]  (reuses g_y)
//   7) proj GEMM + bias (fp32)                       -> d_out
// ---------------------------------------------------------------------------

#if defined(__CUDA_ARCH_FEAT_SM103_ALL) || defined(__CUDA_ARCH_FEAT_SM100_ALL)
#define HAS_TC 1
#else
#define HAS_TC 0
#endif

#define BATCH 2
#define CDIM 512
#define HEADS 8
#define DH 64
#define NPIX 4096
#define TOTAL (BATCH*CDIM*NPIX)
#define QKD 1024

__device__ float g_y[BATCH * CDIM * NPIX];            // 16 MB
__device__ float g_qkvt[BATCH * NPIX * QKD];          // 32 MB  (q,k transposed)
__device__ float g_vt[BATCH * CDIM * NPIX];           // 16 MB  (v standard = V^T)
__device__ float g_ot[BATCH * NPIX * CDIM];           // 16 MB
__device__ float g_wT[CDIM * QKD];                    // 2 MB

// ---------------- f32x2 helpers -------------------------------------------
__device__ __forceinline__ unsigned long long pk2(float lo, float hi) {
    unsigned long long r;
    asm("mov.b64 %0, {%1, %2};" : "=l"(r)
        : "r"(__float_as_uint(lo)), "r"(__float_as_uint(hi)));
    return r;
}
__device__ __forceinline__ void upk2(unsigned long long v, float& lo, float& hi) {
    unsigned int a, b;
    asm("mov.b64 {%0, %1}, %2;" : "=r"(a), "=r"(b) : "l"(v));
    lo = __uint_as_float(a); hi = __uint_as_float(b);
}
__device__ __forceinline__ unsigned long long fma2(unsigned long long a,
                                                   unsigned long long b,
                                                   unsigned long long c) {
    unsigned long long d;
    asm("fma.rn.f32x2 %0, %1, %2, %3;" : "=l"(d) : "l"(a), "l"(b), "l"(c));
    return d;
}
__device__ __forceinline__ unsigned long long mul2(unsigned long long a,
                                                   unsigned long long b) {
    unsigned long long d;
    asm("mul.rn.f32x2 %0, %1, %2;" : "=l"(d) : "l"(a), "l"(b));
    return d;
}

// ---------------- common helpers ------------------------------------------
__device__ __forceinline__ uint32_t smem_u32(const void* p) {
    uint32_t a;
    asm("{ .reg .u64 t; cvta.to.shared.u64 t, %1; cvt.u32.u64 %0, t; }"
        : "=r"(a) : "l"(p));
    return a;
}
__device__ __forceinline__ unsigned short f2bf(float x) {
    return __bfloat16_as_ushort(__float2bfloat16_rn(x));
}
__device__ __forceinline__ float bf2f(unsigned short u) {
    return __bfloat162float(__ushort_as_bfloat16(u));
}
__device__ __forceinline__ float ex2f(float x) {
    float y; asm("ex2.approx.ftz.f32 %0, %1;" : "=f"(y) : "f"(x)); return y;
}
#define SWZ(o) ((o) ^ (((o) >> 3) & 0x70))

#if HAS_TC
// ---------------- tcgen05 helpers (103a pass only) -------------------------
__device__ __forceinline__ unsigned elect1() {
    unsigned p;
    asm volatile("{\n\t.reg .pred p;\n\telect.sync _|p, 0xFFFFFFFF;\n\t"
                 "selp.b32 %0, 1, 0, p;\n\t}" : "=r"(p));
    return p;
}
__device__ __forceinline__ void mma_ss(uint32_t d, unsigned long long a,
                                       unsigned long long b, uint32_t id, uint32_t en) {
    asm volatile("{\n\t.reg .pred p;\n\tsetp.ne.u32 p, %5, 0;\n\t"
        "tcgen05.mma.cta_group::1.kind::f16 [%0], %1, %2, %3, {%4,%4,%4,%4}, p;\n\t}"
        :: "r"(d), "l"(a), "l"(b), "r"(id), "r"(0u), "r"(en) : "memory");
}
__device__ __forceinline__ void tc_commit(uint32_t mbar) {
    asm volatile("tcgen05.commit.cta_group::1.mbarrier::arrive::one.shared::cluster.b64 [%0];"
                 :: "r"(mbar) : "memory");
}
__device__ __forceinline__ void mbar_init1(uint32_t mbar) {
    asm volatile("mbarrier.init.shared.b64 [%0], %1;" :: "r"(mbar), "r"(1u) : "memory");
}
__device__ __forceinline__ void mbar_wait(uint32_t mbar, uint32_t ph) {
    asm volatile("{\n\t.reg .pred P1;\n\tLAB1_%=:\n\t"
        "mbarrier.try_wait.parity.acquire.cta.shared::cta.b64 P1, [%0], %1, 0x989680;\n\t"
        "@P1 bra.uni LAB2_%=;\n\tbra.uni LAB1_%=;\n\tLAB2_%=:\n\t}"
        :: "r"(mbar), "r"(ph) : "memory");
}
#define TCF_AFTER()  asm volatile("tcgen05.fence::after_thread_sync;" ::: "memory")
#define TCF_BEFORE() asm volatile("tcgen05.fence::before_thread_sync;" ::: "memory")
#define FPROXY()     asm volatile("fence.proxy.async.shared::cta;" ::: "memory")
#define TC_WAIT_LD() asm volatile("tcgen05.wait::ld.sync.aligned;" ::: "memory")

#define LDX32(r, ta) \
    asm volatile("tcgen05.ld.sync.aligned.32x32b.x32.b32 " \
        "{%0, %1, %2, %3, %4, %5, %6, %7, %8, %9, %10, %11, %12, %13, %14, %15, " \
        " %16, %17, %18, %19, %20, %21, %22, %23, %24, %25, %26, %27, %28, %29, %30, %31}, [%32];" \
        : "=r"((r)[0]),  "=r"((r)[1]),  "=r"((r)[2]),  "=r"((r)[3]), \
          "=r"((r)[4]),  "=r"((r)[5]),  "=r"((r)[6]),  "=r"((r)[7]), \
          "=r"((r)[8]),  "=r"((r)[9]),  "=r"((r)[10]), "=r"((r)[11]), \
          "=r"((r)[12]), "=r"((r)[13]), "=r"((r)[14]), "=r"((r)[15]), \
          "=r"((r)[16]), "=r"((r)[17]), "=r"((r)[18]), "=r"((r)[19]), \
          "=r"((r)[20]), "=r"((r)[21]), "=r"((r)[22]), "=r"((r)[23]), \
          "=r"((r)[24]), "=r"((r)[25]), "=r"((r)[26]), "=r"((r)[27]), \
          "=r"((r)[28]), "=r"((r)[29]), "=r"((r)[30]), "=r"((r)[31]) \
        : "r"(ta))

#define DESC_K  ((2ull<<61)|(1ull<<46)|(64ull<<32)|(1ull<<16))
__device__ __forceinline__ unsigned long long mkdesc(uint32_t addr) {
    return DESC_K | ((unsigned long long)(addr >> 4) & 0x3FFF);
}
#endif  // HAS_TC

// ---------------- 1) depthwise 3x3 ----------------------------------------
__global__ void k_dwconv(const float* __restrict__ x,
                         const float* __restrict__ w,
                         float* __restrict__ y) {
    int idx = blockIdx.x * blockDim.x + threadIdx.x;
    if (idx >= TOTAL) return;
    int n = idx & (NPIX - 1);
    int c = (idx >> 12) & (CDIM - 1);
    int hh = n >> 6, ww = n & 63;
    const float* xb = x + (long long)(idx >> 12) * NPIX;
    const float* wc = w + c * 9;
    float s = 0.f;
#pragma unroll
    for (int i = 0; i < 3; i++) {
        int h2 = hh + i - 1;
        if ((unsigned)h2 < 64u) {
#pragma unroll
            for (int j = 0; j < 3; j++) {
                int w2 = ww + j - 1;
                if ((unsigned)w2 < 64u) s += xb[h2 * 64 + w2] * wc[i * 3 + j];
            }
        }
    }
    y[idx] = s;
}

// ---------------- transpose src[R][C] -> dst[C][R] -------------------------
__global__ void k_transpose(const float* __restrict__ src, float* __restrict__ dst,
                            int R, int C, long long ss, long long sd) {
    __shared__ float t[32][33];
    const float* s = src + (long long)blockIdx.z * ss;
    float* d = dst + (long long)blockIdx.z * sd;
    int bx = blockIdx.x * 32, by = blockIdx.y * 32;
    int x = bx + threadIdx.x;
#pragma unroll
    for (int j = 0; j < 4; j++) {
        int yy = by + threadIdx.y + j * 8;
        t[threadIdx.y + j * 8][threadIdx.x] = s[(long long)yy * C + x];
    }
    __syncthreads();
    int x2 = by + threadIdx.x;
#pragma unroll
    for (int j = 0; j < 4; j++) {
        int yy = bx + threadIdx.y + j * 8;
        d[(long long)yy * R + x2] = t[threadIdx.x][threadIdx.y + j * 8];
    }
}

// ---------------- GEMM: C[M,N]=A[M,K]@B[K,N] (+bias) -----------------------
__global__ __launch_bounds__(256) void k_gemm64(
    const float* __restrict__ A, const float* __restrict__ B,
    float* __restrict__ C, const float* __restrict__ bias,
    int M, int N, int K, long long sB, long long sC) {
    __shared__ float As[16 * 68];
    __shared__ float Bs[16 * 64];
    int tid = threadIdx.x;
    int ty = tid >> 4, tx = tid & 15;
    int m0 = blockIdx.y * 64, n0 = blockIdx.x * 64;
    const float* Bb = B + (long long)blockIdx.z * sB;
    float* Cb = C + (long long)blockIdx.z * sC;

    unsigned long long acc[4][2];
#pragma unroll
    for (int i = 0; i < 4; i++) { acc[i][0] = 0ull; acc[i][1] = 0ull; }

    for (int k0 = 0; k0 < K; k0 += 16) {
#pragma unroll
        for (int l = 0; l < 4; l++) {
            int idx = tid + l * 256;
            int m = idx >> 4, kk = idx & 15;
            As[kk * 68 + m] = A[(long long)(m0 + m) * K + k0 + kk];
            int kb = idx >> 6, nn = idx & 63;
            Bs[kb * 64 + nn] = Bb[(long long)(k0 + kb) * N + n0 + nn];
        }
        __syncthreads();
#pragma unroll
        for (int kk = 0; kk < 16; kk++) {
            float4 a4 = *(const float4*)&As[kk * 68 + ty * 4];
            float4 b4 = *(const float4*)&Bs[kk * 64 + tx * 4];
            unsigned long long b0 = pk2(b4.x, b4.y);
            unsigned long long b1 = pk2(b4.z, b4.w);
            float av[4] = {a4.x, a4.y, a4.z, a4.w};
#pragma unroll
            for (int i = 0; i < 4; i++) {
                unsigned long long ap = pk2(av[i], av[i]);
                acc[i][0] = fma2(ap, b0, acc[i][0]);
                acc[i][1] = fma2(ap, b1, acc[i][1]);
            }
        }
        __syncthreads();
    }
#pragma unroll
    for (int i = 0; i < 4; i++) {
        float c0, c1, c2, c3;
        upk2(acc[i][0], c0, c1);
        upk2(acc[i][1], c2, c3);
        float bv = bias ? bias[m0 + ty * 4 + i] : 0.f;
        float4 o = make_float4(c0 + bv, c1 + bv, c2 + bv, c3 + bv);
        *(float4*)&Cb[(long long)(m0 + ty * 4 + i) * N + n0 + tx * 4] = o;
    }
}

// ---------------- GEMM-T: Ct[m,n] = sum_k Y[k,m] * WT[k,n] -----------------
__global__ __launch_bounds__(256) void k_gemmT(
    const float* __restrict__ Y, const float* __restrict__ WT,
    float* __restrict__ Ct, int M, int N, int K, long long sY, long long sC) {
    __shared__ float As[16 * 68];
    __shared__ float Bs[16 * 64];
    int tid = threadIdx.x;
    int ty = tid >> 4, tx = tid & 15;
    int m0 = blockIdx.y * 64, n0 = blockIdx.x * 64;
    const float* Yb = Y + (long long)blockIdx.z * sY;
    float* Cb = Ct + (long long)blockIdx.z * sC;

    unsigned long long acc[4][2];
#pragma unroll
    for (int i = 0; i < 4; i++) { acc[i][0] = 0ull; acc[i][1] = 0ull; }

    for (int k0 = 0; k0 < K; k0 += 16) {
#pragma unroll
        for (int l = 0; l < 4; l++) {
            int idx = tid + l * 256;
            int m = idx & 63, kk = idx >> 6;
            As[kk * 68 + m] = Yb[(long long)(k0 + kk) * M + m0 + m];
            Bs[kk * 64 + m] = WT[(long long)(k0 + kk) * N + n0 + m];
        }
        __syncthreads();
#pragma unroll
        for (int kk = 0; kk < 16; kk++) {
            float4 a4 = *(const float4*)&As[kk * 68 + ty * 4];
            float4 b4 = *(const float4*)&Bs[kk * 64 + tx * 4];
            unsigned long long b0 = pk2(b4.x, b4.y);
            unsigned long long b1 = pk2(b4.z, b4.w);
            float av[4] = {a4.x, a4.y, a4.z, a4.w};
#pragma unroll
            for (int i = 0; i < 4; i++) {
                unsigned long long ap = pk2(av[i], av[i]);
                acc[i][0] = fma2(ap, b0, acc[i][0]);
                acc[i][1] = fma2(ap, b1, acc[i][1]);
            }
        }
        __syncthreads();
    }
#pragma unroll
    for (int i = 0; i < 4; i++) {
        float c0, c1, c2, c3;
        upk2(acc[i][0], c0, c1);
        upk2(acc[i][1], c2, c3);
        float4 o = make_float4(c0, c1, c2, c3);
        *(float4*)&Cb[(long long)(m0 + ty * 4 + i) * N + n0 + tx * 4] = o;
    }
}

// ---------------- attention ------------------------------------------------
// CTA = (128 q rows, head, batch).
// qkvt[n,1024]: q at col h*64, k at col 512+h*64.  vt[c][n] = V^T per head.
#define SM_TMEMPTR 0
#define SM_MBAR 8
#define SM_QHI 1024
#define SM_QLO (SM_QHI + 16384)
#define SM_KHI (SM_QLO + 16384)
#define SM_KLO (SM_KHI + 8192)
#define SM_VHI (SM_KLO + 8192)
#define SM_VLO (SM_VHI + 8192)
#define SM_PHI (SM_VLO + 8192)
#define SM_PLO (SM_PHI + 16384)
#define ATT_SMEM_TC (SM_PLO + 16384)
#define ATT_SMEM_FB ((64*64 + 64*64 + 64*68 + 64*66) * 4)
#define ATT_SMEM (ATT_SMEM_TC > ATT_SMEM_FB ? ATT_SMEM_TC : ATT_SMEM_FB)

#define TM_S 0
#define TM_O 64
#define TM_COLS 128

// kind::f16 idesc: fp32 acc, bf16 a/b, N=64, M=128  (pattern == 0x8080490 form)
#define IDESC ((1u<<4)|(1u<<7)|(1u<<10)|(8u<<17)|(8u<<24))

#define ATT_SCALE_L2E 0.18033688f   /* 0.125 * log2(e) */

__global__ void __launch_bounds__(256) k_attn(const float* __restrict__ qkvt,
                                              const float* __restrict__ vt,
                                              float* __restrict__ ot) {
#if HAS_TC
    // ======================= tcgen05 path (all SS, K-major) ================
    extern __shared__ char sm[];
    uint32_t sb = smem_u32(sm);
    int tid = threadIdx.x, wid = tid >> 5;
    int n0 = blockIdx.x * 128;
    int h = blockIdx.y, b = blockIdx.z;
    const float* qkb = qkvt + (long long)b * NPIX * QKD;
    const float* vtb = vt + (long long)b * CDIM * NPIX + (long long)h * DH * NPIX;

    if (wid == 0) {
        asm volatile("tcgen05.alloc.cta_group::1.sync.aligned.shared::cta.b32 [%0], %1;"
                     :: "r"(sb + SM_TMEMPTR), "r"((uint32_t)TM_COLS) : "memory");
    }
    if (tid == 0) mbar_init1(sb + SM_MBAR);
    __syncthreads();
    uint32_t tb;
    asm volatile("ld.shared.b32 %0, [%1];" : "=r"(tb) : "r"(sb + SM_TMEMPTR));

    // ---- Q tile (128 x 64), scale*log2e folded, bf16 split, SW128 ----
#pragma unroll
    for (int l = 0; l < 8; l++) {
        int g = tid + l * 256;
        int r = g >> 4, dq = g & 15;
        float4 v = *(const float4*)(qkb + (long long)(n0 + r) * QKD + h * DH + dq * 4);
        v.x *= ATT_SCALE_L2E; v.y *= ATT_SCALE_L2E; v.z *= ATT_SCALE_L2E; v.w *= ATT_SCALE_L2E;
        unsigned short h0 = f2bf(v.x), h1 = f2bf(v.y), h2 = f2bf(v.z), h3 = f2bf(v.w);
        uint32_t off = SWZ((uint32_t)(r * 128 + dq * 8));
        *(uint2*)(sm + SM_QHI + off) =
            make_uint2((uint32_t)h0 | ((uint32_t)h1 << 16), (uint32_t)h2 | ((uint32_t)h3 << 16));
        unsigned short l0 = f2bf(v.x - bf2f(h0)), l1 = f2bf(v.y - bf2f(h1));
        unsigned short l2 = f2bf(v.z - bf2f(h2)), l3 = f2bf(v.w - bf2f(h3));
        *(uint2*)(sm + SM_QLO + off) =
            make_uint2((uint32_t)l0 | ((uint32_t)l1 << 16), (uint32_t)l2 | ((uint32_t)l3 << 16));
    }
    FPROXY();
    __syncthreads();

    unsigned long long aQhi = mkdesc(sb + SM_QHI);
    unsigned long long aQlo = mkdesc(sb + SM_QLO);
    unsigned long long bKhi = mkdesc(sb + SM_KHI);
    unsigned long long bKlo = mkdesc(sb + SM_KLO);
    unsigned long long bVhi = mkdesc(sb + SM_VHI);
    unsigned long long bVlo = mkdesc(sb + SM_VLO);
    unsigned long long aPhi = mkdesc(sb + SM_PHI);
    unsigned long long aPlo = mkdesc(sb + SM_PLO);

    float den = 0.f;
    uint32_t ph = 0;

    for (int t = 0; t < 64; t++) {
        if (t) { mbar_wait(sb + SM_MBAR, ph); ph ^= 1; }   // prev AV done
        int m0 = t * 64;

        // ---- K tile (64 keys x 64 d), K-major rows = keys ----
#pragma unroll
        for (int l = 0; l < 4; l++) {
            int g = tid + l * 256;
            int c = g >> 4, dq = g & 15;
            float4 kv = *(const float4*)(qkb + (long long)(m0 + c) * QKD + 512 + h * DH + dq * 4);
            uint32_t off = SWZ((uint32_t)(c * 128 + dq * 8));
            unsigned short h0 = f2bf(kv.x), h1 = f2bf(kv.y), h2 = f2bf(kv.z), h3 = f2bf(kv.w);
            *(uint2*)(sm + SM_KHI + off) =
                make_uint2((uint32_t)h0 | ((uint32_t)h1 << 16), (uint32_t)h2 | ((uint32_t)h3 << 16));
            unsigned short l0 = f2bf(kv.x - bf2f(h0)), l1 = f2bf(kv.y - bf2f(h1));
            unsigned short l2 = f2bf(kv.z - bf2f(h2)), l3 = f2bf(kv.w - bf2f(h3));
            *(uint2*)(sm + SM_KLO + off) =
                make_uint2((uint32_t)l0 | ((uint32_t)l1 << 16), (uint32_t)l2 | ((uint32_t)l3 << 16));
        }
        // ---- V^T tile (64 d x 64 keys), K-major rows = d, coalesced ----
#pragma unroll
        for (int l = 0; l < 4; l++) {
            int g = tid + l * 256;
            int d = g >> 4, kq = g & 15;
            float4 vv = *(const float4*)(vtb + (long long)d * NPIX + m0 + kq * 4);
            uint32_t off = SWZ((uint32_t)(d * 128 + kq * 8));
            unsigned short h0 = f2bf(vv.x), h1 = f2bf(vv.y), h2 = f2bf(vv.z), h3 = f2bf(vv.w);
            *(uint2*)(sm + SM_VHI + off) =
                make_uint2((uint32_t)h0 | ((uint32_t)h1 << 16), (uint32_t)h2 | ((uint32_t)h3 << 16));
            unsigned short l0 = f2bf(vv.x - bf2f(h0)), l1 = f2bf(vv.y - bf2f(h1));
            unsigned short l2 = f2bf(vv.z - bf2f(h2)), l3 = f2bf(vv.w - bf2f(h3));
            *(uint2*)(sm + SM_VLO + off) =
                make_uint2((uint32_t)l0 | ((uint32_t)l1 << 16), (uint32_t)l2 | ((uint32_t)l3 << 16));
        }
        FPROXY();
        __syncthreads();

        // ---- S = Q @ K^T (SS, 3 split products x 4 K-steps) ----
        if (wid == 0) {
            if (elect1()) {
#pragma unroll
                for (int ks = 0; ks < 4; ks++)
                    mma_ss(tb + TM_S, aQhi + ks * 2, bKhi + ks * 2, IDESC, ks > 0);
#pragma unroll
                for (int ks = 0; ks < 4; ks++)
                    mma_ss(tb + TM_S, aQhi + ks * 2, bKlo + ks * 2, IDESC, 1u);
#pragma unroll
                for (int ks = 0; ks < 4; ks++)
                    mma_ss(tb + TM_S, aQlo + ks * 2, bKhi + ks * 2, IDESC, 1u);
                tc_commit(sb + SM_MBAR);
            }
        }
        mbar_wait(sb + SM_MBAR, ph); ph ^= 1;

        // ---- softmax: thread owns q-row = tid (warps 0-3) ----
        if (tid < 128) {
            TCF_AFTER();
            uint32_t sr[64];
            LDX32(sr, tb + TM_S);
            LDX32(sr + 32, tb + TM_S + 32);
            TC_WAIT_LD();
            float p[64];
#pragma unroll
            for (int c = 0; c < 64; c++) p[c] = ex2f(__uint_as_float(sr[c]));
            float dsum = 0.f;
#pragma unroll
            for (int c = 0; c < 64; c++) dsum += p[c];
            den += dsum;

            // write P row (bf16 hi/lo) to SW128 smem: row tid, 64 keys = 128B
            uint32_t rbase = (uint32_t)(tid * 128);
#pragma unroll
            for (int j = 0; j < 32; j++) {
                unsigned short a = f2bf(p[2 * j]), c = f2bf(p[2 * j + 1]);
                *(uint32_t*)(sm + SM_PHI + SWZ(rbase + j * 4)) =
                    (uint32_t)a | ((uint32_t)c << 16);
            }
#pragma unroll
            for (int j = 0; j < 32; j++) {
                unsigned short a = f2bf(p[2 * j] - bf2f(f2bf(p[2 * j])));
                unsigned short c = f2bf(p[2 * j + 1] - bf2f(f2bf(p[2 * j + 1])));
                *(uint32_t*)(sm + SM_PLO + SWZ(rbase + j * 4)) =
                    (uint32_t)a | ((uint32_t)c << 16);
            }
            FPROXY();
        }
        __syncthreads();

        // ---- O += P @ (V^T)^T (SS, 3 split products x 4 K-steps) ----
        if (wid == 0) {
            if (elect1()) {
#pragma unroll
                for (int ks = 0; ks < 4; ks++)
                    mma_ss(tb + TM_O, aPhi + ks * 2, bVhi + ks * 2, IDESC,
                           (t > 0 || ks > 0) ? 1u : 0u);
#pragma unroll
                for (int ks = 0; ks < 4; ks++)
                    mma_ss(tb + TM_O, aPhi + ks * 2, bVlo + ks * 2, IDESC, 1u);
#pragma unroll
                for (int ks = 0; ks < 4; ks++)
                    mma_ss(tb + TM_O, aPlo + ks * 2, bVhi + ks * 2, IDESC, 1u);
                tc_commit(sb + SM_MBAR);
            }
        }
    }
    mbar_wait(sb + SM_MBAR, ph); ph ^= 1;

    // ---- epilogue: O / den -> ot[n, c] ----
    if (tid < 128) {
        TCF_AFTER();
        uint32_t orr[64];
        LDX32(orr, tb + TM_O);
        LDX32(orr + 32, tb + TM_O + 32);
        TC_WAIT_LD();
        float inv = 1.0f / den;
        float* dst = ot + ((long long)b * NPIX + n0 + tid) * CDIM + h * DH;
#pragma unroll
        for (int j = 0; j < 16; j++) {
            float4 v = make_float4(__uint_as_float(orr[4 * j]) * inv,
                                   __uint_as_float(orr[4 * j + 1]) * inv,
                                   __uint_as_float(orr[4 * j + 2]) * inv,
                                   __uint_as_float(orr[4 * j + 3]) * inv);
            ((float4*)dst)[j] = v;
        }
    }
    __syncthreads();
    if (wid == 0) {
        asm volatile("tcgen05.dealloc.cta_group::1.sync.aligned.b32 %0, %1;"
                     :: "r"(tb), "r"((uint32_t)TM_COLS));
    }
#else
    // ======================= fp32 fallback =================================
    extern __shared__ float smf[];
    float* Qs = smf;                 // [d*64 + r]
    float* Ks = Qs + 64 * 64;        // [d*64 + c]
    float* Vs = Ks + 64 * 64;        // [c*68 + d]
    float* Ps = Vs + 64 * 68;        // [r*66 + c]

    int tid = threadIdx.x;
    int ty = tid >> 4, tx = tid & 15;
    int h = blockIdx.y, b = blockIdx.z;
    const float* qkb = qkvt + (long long)b * NPIX * QKD;
    const float* vtb = vt + (long long)b * CDIM * NPIX + (long long)h * DH * NPIX;

    for (int qt = 0; qt < 2; qt++) {
        int n0 = blockIdx.x * 128 + qt * 64;
        __syncthreads();
#pragma unroll
        for (int l = 0; l < 4; l++) {
            int g = tid + l * 256;
            int r = g >> 4, dq = g & 15;
            float4 v = *(const float4*)(qkb + (long long)(n0 + r) * QKD + h * DH + dq * 4);
            Qs[(dq * 4 + 0) * 64 + r] = v.x * 0.125f;
            Qs[(dq * 4 + 1) * 64 + r] = v.y * 0.125f;
            Qs[(dq * 4 + 2) * 64 + r] = v.z * 0.125f;
            Qs[(dq * 4 + 3) * 64 + r] = v.w * 0.125f;
        }

        float m_run[4], l_run[4];
        unsigned long long acc[4][2];
#pragma unroll
        for (int i = 0; i < 4; i++) {
            m_run[i] = -1e30f; l_run[i] = 0.f; acc[i][0] = 0ull; acc[i][1] = 0ull;
        }

        for (int m0 = 0; m0 < NPIX; m0 += 64) {
            __syncthreads();
#pragma unroll
            for (int l = 0; l < 4; l++) {
                int g = tid + l * 256;
                int c = g >> 4, dq = g & 15;
                float4 kv = *(const float4*)(qkb + (long long)(m0 + c) * QKD + 512 + h * DH + dq * 4);
                Ks[(dq * 4 + 0) * 64 + c] = kv.x;
                Ks[(dq * 4 + 1) * 64 + c] = kv.y;
                Ks[(dq * 4 + 2) * 64 + c] = kv.z;
                Ks[(dq * 4 + 3) * 64 + c] = kv.w;
                Vs[c * 68 + dq * 4 + 0] = vtb[(long long)(dq * 4 + 0) * NPIX + m0 + c];
                Vs[c * 68 + dq * 4 + 1] = vtb[(long long)(dq * 4 + 1) * NPIX + m0 + c];
                Vs[c * 68 + dq * 4 + 2] = vtb[(long long)(dq * 4 + 2) * NPIX + m0 + c];
                Vs[c * 68 + dq * 4 + 3] = vtb[(long long)(dq * 4 + 3) * NPIX + m0 + c];
            }
            __syncthreads();

            unsigned long long s2[4][2];
#pragma unroll
            for (int i = 0; i < 4; i++) { s2[i][0] = 0ull; s2[i][1] = 0ull; }
#pragma unroll 8
            for (int d = 0; d < 64; d++) {
                float4 a4 = *(const float4*)&Qs[d * 64 + ty * 4];
                float4 b4 = *(const float4*)&Ks[d * 64 + tx * 4];
                unsigned long long b0 = pk2(b4.x, b4.y);
                unsigned long long b1 = pk2(b4.z, b4.w);
                float av[4] = {a4.x, a4.y, a4.z, a4.w};
#pragma unroll
                for (int i = 0; i < 4; i++) {
                    unsigned long long ap = pk2(av[i], av[i]);
                    s2[i][0] = fma2(ap, b0, s2[i][0]);
                    s2[i][1] = fma2(ap, b1, s2[i][1]);
                }
            }

#pragma unroll
            for (int i = 0; i < 4; i++) {
                float s0, s1, s2f, s3;
                upk2(s2[i][0], s0, s1);
                upk2(s2[i][1], s2f, s3);
                float tm = fmaxf(fmaxf(s0, s1), fmaxf(s2f, s3));
                tm = fmaxf(tm, __shfl_xor_sync(0xffffffffu, tm, 1));
                tm = fmaxf(tm, __shfl_xor_sync(0xffffffffu, tm, 2));
                tm = fmaxf(tm, __shfl_xor_sync(0xffffffffu, tm, 4));
                tm = fmaxf(tm, __shfl_xor_sync(0xffffffffu, tm, 8));
                float mn = fmaxf(m_run[i], tm);
                float f = __expf(m_run[i] - mn);
                float p0 = __expf(s0 - mn);
                float p1 = __expf(s1 - mn);
                float p2 = __expf(s2f - mn);
                float p3 = __expf(s3 - mn);
                float rs = (p0 + p1) + (p2 + p3);
                rs += __shfl_xor_sync(0xffffffffu, rs, 1);
                rs += __shfl_xor_sync(0xffffffffu, rs, 2);
                rs += __shfl_xor_sync(0xffffffffu, rs, 4);
                rs += __shfl_xor_sync(0xffffffffu, rs, 8);
                l_run[i] = l_run[i] * f + rs;
                m_run[i] = mn;
                unsigned long long fp = pk2(f, f);
                acc[i][0] = mul2(acc[i][0], fp);
                acc[i][1] = mul2(acc[i][1], fp);
                int r = ty * 4 + i;
                Ps[r * 66 + tx * 4 + 0] = p0;
                Ps[r * 66 + tx * 4 + 1] = p1;
                Ps[r * 66 + tx * 4 + 2] = p2;
                Ps[r * 66 + tx * 4 + 3] = p3;
            }
            __syncthreads();

#pragma unroll 4
            for (int c = 0; c < 64; c += 2) {
                float4 va = *(const float4*)&Vs[c * 68 + tx * 4];
                float4 vb = *(const float4*)&Vs[(c + 1) * 68 + tx * 4];
                unsigned long long va0 = pk2(va.x, va.y);
                unsigned long long va1 = pk2(va.z, va.w);
                unsigned long long vb0 = pk2(vb.x, vb.y);
                unsigned long long vb1 = pk2(vb.z, vb.w);
#pragma unroll
                for (int i = 0; i < 4; i++) {
                    float2 pr = *(const float2*)&Ps[(ty * 4 + i) * 66 + c];
                    unsigned long long pa = pk2(pr.x, pr.x);
                    unsigned long long pb = pk2(pr.y, pr.y);
                    acc[i][0] = fma2(pa, va0, acc[i][0]);
                    acc[i][1] = fma2(pa, va1, acc[i][1]);
                    acc[i][0] = fma2(pb, vb0, acc[i][0]);
                    acc[i][1] = fma2(pb, vb1, acc[i][1]);
                }
            }
        }

#pragma unroll
        for (int i = 0; i < 4; i++) {
            float inv = 1.0f / l_run[i];
            float c0, c1, c2, c3;
            upk2(acc[i][0], c0, c1);
            upk2(acc[i][1], c2, c3);
            float* dst = ot + ((long long)b * NPIX + n0 + ty * 4 + i) * CDIM + h * DH;
            *(float4*)(dst + tx * 4) = make_float4(c0 * inv, c1 * inv, c2 * inv, c3 * inv);
        }
    }
#endif
}

// ---------------------------------------------------------------------------
extern "C" void kernel_launch(void* const* d_in, const int* in_sizes, int n_in,
                              void* d_out, int out_size) {
    const float* x      = (const float*)d_in[0];
    const float* dw_w   = (const float*)d_in[1];
    const float* qkv_w  = (const float*)d_in[2];
    const float* proj_w = (const float*)d_in[3];
    const float* proj_b = (const float*)d_in[4];
    float* out = (float*)d_out;

    float *py, *pqkvt, *pvt, *pot, *pwT;
    cudaGetSymbolAddress((void**)&py,    g_y);
    cudaGetSymbolAddress((void**)&pqkvt, g_qkvt);
    cudaGetSymbolAddress((void**)&pvt,   g_vt);
    cudaGetSymbolAddress((void**)&pot,   g_ot);
    cudaGetSymbolAddress((void**)&pwT,   g_wT);

    cudaFuncSetAttribute(k_attn, cudaFuncAttributeMaxDynamicSharedMemorySize,
                         ATT_SMEM);

    // 1) depthwise conv
    k_dwconv<<<(TOTAL + 255) / 256, 256>>>(x, dw_w, py);

    // 2) transpose qkv_w rows 0..1023 (q,k weights) -> wT [512][1024]
    {
        dim3 grid(CDIM / 32, QKD / 32, 1);
        k_transpose<<<grid, dim3(32, 8)>>>(qkv_w, pwT, QKD, CDIM, 0, 0);
    }

    // 3) qk GEMM transposed: qkvt[n, 1024]
    {
        dim3 grid(QKD / 64, NPIX / 64, BATCH);
        k_gemmT<<<grid, 256>>>(py, pwT, pqkvt, NPIX, QKD, CDIM,
                               (long long)CDIM * NPIX,
                               (long long)NPIX * QKD);
    }

    // 4) V GEMM, standard layout (= V^T per head): vt[c][n]
    {
        dim3 grid(NPIX / 64, CDIM / 64, BATCH);
        k_gemm64<<<grid, 256>>>(qkv_w + 1024 * CDIM, py, pvt, nullptr,
                                CDIM, NPIX, CDIM,
                                (long long)CDIM * NPIX,
                                (long long)CDIM * NPIX);
    }

    // 5) attention -> ot[n, c]
    {
        dim3 grid(NPIX / 128, HEADS, BATCH);
        k_attn<<<grid, 256, ATT_SMEM>>>(pqkvt, pvt, pot);
    }

    // 6) transpose ot (4096x512) -> [c][n], reuse g_y
    {
        dim3 grid(CDIM / 32, NPIX / 32, BATCH);
        k_transpose<<<grid, dim3(32, 8)>>>(pot, py, NPIX, CDIM,
                                           (long long)NPIX * CDIM,
                                           (long long)CDIM * NPIX);
    }

    // 7) proj GEMM + bias
    {
        dim3 grid(NPIX / 64, CDIM / 64, BATCH);
        k_gemm64<<<grid, 256>>>(proj_w, py, out, proj_b,
                                CDIM, NPIX, CDIM,
                                (long long)CDIM * NPIX,
                                (long long)CDIM * NPIX);
    }
}

// round 5
// speedup vs baseline: 4.6731x; 1.5033x over previous
#include <cuda_runtime.h>
#include <cuda_bf16.h>
#include <cstdint>

// ---------------------------------------------------------------------------
// LightweightSelfAttention  (B=2, C=512, H=W=64, heads=8, dh=64)
// All-tcgen05 pipeline, bf16 2-way-split everywhere (fp32-grade accuracy):
//   1) depthwise 3x3 conv                      x -> g_y [c][n] fp32
//   2) k_cvt: qkv_w, proj_w -> bf16 hi/lo      (row-major [o][512], K-major)
//   3) k_t2bf: y -> yT bf16 hi/lo [n][512]
//   4) k_gemm_tc qk:  qkt[n][1024]  (q cols pre-scaled by 0.125*log2e)
//   5) k_gemm_tc v:   vt[c][n]      (per head = V^T, K-major for AV MMA)
//   6) k_attn  (tcgen05, no-max softmax)  -> ot[n][512] bf16 hi/lo
//   7) k_gemm_tc proj: out[c][n] fp32 + bias
// ---------------------------------------------------------------------------

#if defined(__CUDA_ARCH_FEAT_SM103_ALL) || defined(__CUDA_ARCH_FEAT_SM100_ALL)
#define HAS_TC 1
#else
#define HAS_TC 0
#endif

#define BATCH 2
#define CDIM 512
#define HEADS 8
#define DH 64
#define NPIX 4096
#define TOTAL (BATCH*CDIM*NPIX)
#define QKD 1024

typedef unsigned short u16;
typedef unsigned int u32;
typedef unsigned long long u64;

__device__ float g_y[BATCH * CDIM * NPIX];                  // 16 MB
__device__ u16 g_ythi[BATCH * NPIX * CDIM];                 // 8 MB
__device__ u16 g_ytlo[BATCH * NPIX * CDIM];
__device__ u16 g_whi[3 * CDIM * CDIM];                      // qkv_w split
__device__ u16 g_wlo[3 * CDIM * CDIM];
__device__ u16 g_pwhi[CDIM * CDIM];                         // proj_w split
__device__ u16 g_pwlo[CDIM * CDIM];
__device__ u16 g_qkthi[BATCH * NPIX * QKD];                 // 16 MB
__device__ u16 g_qktlo[BATCH * NPIX * QKD];
__device__ u16 g_vthi[BATCH * CDIM * NPIX];                 // 8 MB
__device__ u16 g_vtlo[BATCH * CDIM * NPIX];
__device__ u16 g_othi[BATCH * NPIX * CDIM];
__device__ u16 g_otlo[BATCH * NPIX * CDIM];

#define ATT_SCALE_L2E 0.18033688f   /* 0.125 * log2(e) */

// ---------------- helpers --------------------------------------------------
__device__ __forceinline__ uint32_t smem_u32(const void* p) {
    uint32_t a;
    asm("{ .reg .u64 t; cvta.to.shared.u64 t, %1; cvt.u32.u64 %0, t; }"
        : "=r"(a) : "l"(p));
    return a;
}
__device__ __forceinline__ u16 f2bf(float x) {
    return __bfloat16_as_ushort(__float2bfloat16_rn(x));
}
__device__ __forceinline__ float bf2f(u16 u) {
    return __bfloat162float(__ushort_as_bfloat16(u));
}
__device__ __forceinline__ float ex2f(float x) {
    float y; asm("ex2.approx.ftz.f32 %0, %1;" : "=f"(y) : "f"(x)); return y;
}
#define SWZ(o) ((o) ^ (((o) >> 3) & 0x70))

#if HAS_TC
__device__ __forceinline__ unsigned elect1() {
    unsigned p;
    asm volatile("{\n\t.reg .pred p;\n\telect.sync _|p, 0xFFFFFFFF;\n\t"
                 "selp.b32 %0, 1, 0, p;\n\t}" : "=r"(p));
    return p;
}
__device__ __forceinline__ void mma_ss(uint32_t d, u64 a, u64 b, uint32_t id, uint32_t en) {
    asm volatile("{\n\t.reg .pred p;\n\tsetp.ne.u32 p, %5, 0;\n\t"
        "tcgen05.mma.cta_group::1.kind::f16 [%0], %1, %2, %3, {%4,%4,%4,%4}, p;\n\t}"
        :: "r"(d), "l"(a), "l"(b), "r"(id), "r"(0u), "r"(en) : "memory");
}
__device__ __forceinline__ void tc_commit(uint32_t mbar) {
    asm volatile("tcgen05.commit.cta_group::1.mbarrier::arrive::one.shared::cluster.b64 [%0];"
                 :: "r"(mbar) : "memory");
}
__device__ __forceinline__ void mbar_init1(uint32_t mbar) {
    asm volatile("mbarrier.init.shared.b64 [%0], %1;" :: "r"(mbar), "r"(1u) : "memory");
}
__device__ __forceinline__ void mbar_wait(uint32_t mbar, uint32_t ph) {
    asm volatile("{\n\t.reg .pred P1;\n\tLAB1_%=:\n\t"
        "mbarrier.try_wait.parity.acquire.cta.shared::cta.b64 P1, [%0], %1, 0x989680;\n\t"
        "@P1 bra.uni LAB2_%=;\n\tbra.uni LAB1_%=;\n\tLAB2_%=:\n\t}"
        :: "r"(mbar), "r"(ph) : "memory");
}
#define TCF_AFTER()  asm volatile("tcgen05.fence::after_thread_sync;" ::: "memory")
#define FPROXY()     asm volatile("fence.proxy.async.shared::cta;" ::: "memory")
#define TC_WAIT_LD() asm volatile("tcgen05.wait::ld.sync.aligned;" ::: "memory")

#define LDX32(r, ta) \
    asm volatile("tcgen05.ld.sync.aligned.32x32b.x32.b32 " \
        "{%0, %1, %2, %3, %4, %5, %6, %7, %8, %9, %10, %11, %12, %13, %14, %15, " \
        " %16, %17, %18, %19, %20, %21, %22, %23, %24, %25, %26, %27, %28, %29, %30, %31}, [%32];" \
        : "=r"((r)[0]),  "=r"((r)[1]),  "=r"((r)[2]),  "=r"((r)[3]), \
          "=r"((r)[4]),  "=r"((r)[5]),  "=r"((r)[6]),  "=r"((r)[7]), \
          "=r"((r)[8]),  "=r"((r)[9]),  "=r"((r)[10]), "=r"((r)[11]), \
          "=r"((r)[12]), "=r"((r)[13]), "=r"((r)[14]), "=r"((r)[15]), \
          "=r"((r)[16]), "=r"((r)[17]), "=r"((r)[18]), "=r"((r)[19]), \
          "=r"((r)[20]), "=r"((r)[21]), "=r"((r)[22]), "=r"((r)[23]), \
          "=r"((r)[24]), "=r"((r)[25]), "=r"((r)[26]), "=r"((r)[27]), \
          "=r"((r)[28]), "=r"((r)[29]), "=r"((r)[30]), "=r"((r)[31]) \
        : "r"(ta))

#define DESC_K  ((2ull<<61)|(1ull<<46)|(64ull<<32)|(1ull<<16))
__device__ __forceinline__ u64 mkdesc(uint32_t addr) {
    return DESC_K | ((u64)(addr >> 4) & 0x3FFF);
}
// kind::f16 idesc: fp32 acc, bf16 a/b, N=64, M=128
#define IDESC ((1u<<4)|(1u<<7)|(1u<<10)|(8u<<17)|(8u<<24))
#endif  // HAS_TC

// ---------------- 1) depthwise 3x3 ----------------------------------------
__global__ void k_dwconv(const float* __restrict__ x,
                         const float* __restrict__ w,
                         float* __restrict__ y) {
    int idx = blockIdx.x * blockDim.x + threadIdx.x;
    if (idx >= TOTAL) return;
    int n = idx & (NPIX - 1);
    int c = (idx >> 12) & (CDIM - 1);
    int hh = n >> 6, ww = n & 63;
    const float* xb = x + (long long)(idx >> 12) * NPIX;
    const float* wc = w + c * 9;
    float s = 0.f;
#pragma unroll
    for (int i = 0; i < 3; i++) {
        int h2 = hh + i - 1;
        if ((unsigned)h2 < 64u) {
#pragma unroll
            for (int j = 0; j < 3; j++) {
                int w2 = ww + j - 1;
                if ((unsigned)w2 < 64u) s += xb[h2 * 64 + w2] * wc[i * 3 + j];
            }
        }
    }
    y[idx] = s;
}

// ---------------- 2) elementwise fp32 -> bf16 hi/lo ------------------------
__global__ void k_cvt(const float* __restrict__ src, u16* __restrict__ hi,
                      u16* __restrict__ lo, int n) {
    int i = blockIdx.x * blockDim.x + threadIdx.x;
    if (i >= n) return;
    float v = src[i];
    u16 h = f2bf(v);
    hi[i] = h;
    lo[i] = f2bf(v - bf2f(h));
}

// ---------------- 3) transpose+split: y[c][n] -> yT[n][c] hi/lo ------------
__global__ void k_t2bf(const float* __restrict__ y, u16* __restrict__ thi,
                       u16* __restrict__ tlo) {
    __shared__ float t[32][33];
    long long zo = (long long)blockIdx.z * CDIM * NPIX;
    long long zt = (long long)blockIdx.z * NPIX * CDIM;
    int c0 = blockIdx.y * 32, n0 = blockIdx.x * 32;
#pragma unroll
    for (int j = 0; j < 4; j++) {
        int c = c0 + threadIdx.y + j * 8;
        t[threadIdx.y + j * 8][threadIdx.x] = y[zo + (long long)c * NPIX + n0 + threadIdx.x];
    }
    __syncthreads();
#pragma unroll
    for (int j = 0; j < 4; j++) {
        int n = n0 + threadIdx.y + j * 8;
        float v = t[threadIdx.x][threadIdx.y + j * 8];
        u16 h = f2bf(v);
        thi[zt + (long long)n * CDIM + c0 + threadIdx.x] = h;
        tlo[zt + (long long)n * CDIM + c0 + threadIdx.x] = f2bf(v - bf2f(h));
    }
}

// ---------------- 4/5/7) tcgen05 GEMM --------------------------------------
// D[128 x 64] = A[128 rows, 512] @ B[64 rows, 512]^T, bf16-split 3 products.
// A/B row-major, row stride 512 elements (uint4 stride 64).
// Output: if Ofp: fp32 + bias[m];  else bf16 hi/lo with scale (q cols).
#define GM_TMEMPTR 0
#define GM_MBAR 8
#define GM_AHI 1024
#define GM_ALO (GM_AHI + 16384)
#define GM_BHI (GM_ALO + 16384)
#define GM_BLO (GM_BHI + 8192)
#define GM_SMEM (GM_BLO + 8192)

__global__ void __launch_bounds__(256) k_gemm_tc(
    const uint4* __restrict__ Ahi, const uint4* __restrict__ Alo, long long sA,
    const uint4* __restrict__ Bhi, const uint4* __restrict__ Blo, long long sB,
    u16* __restrict__ Ohi, u16* __restrict__ Olo,
    float* __restrict__ Ofp, const float* __restrict__ bias,
    long long sO, int ldo, float scale_q, int qcols) {
#if HAS_TC
    extern __shared__ char sm[];
    uint32_t sb = smem_u32(sm);
    int tid = threadIdx.x, wid = tid >> 5;
    int mrow0 = blockIdx.x * 128;
    int brow0 = blockIdx.y * 64;
    const uint4* Ah = Ahi + blockIdx.z * sA + (long long)mrow0 * 64;
    const uint4* Al = Alo + blockIdx.z * sA + (long long)mrow0 * 64;
    const uint4* Bh = Bhi + blockIdx.z * sB + (long long)brow0 * 64;
    const uint4* Bl = Blo + blockIdx.z * sB + (long long)brow0 * 64;

    if (wid == 0) {
        asm volatile("tcgen05.alloc.cta_group::1.sync.aligned.shared::cta.b32 [%0], %1;"
                     :: "r"(sb + GM_TMEMPTR), "r"(128u) : "memory");
    }
    if (tid == 0) mbar_init1(sb + GM_MBAR);
    __syncthreads();
    uint32_t tb;
    asm volatile("ld.shared.b32 %0, [%1];" : "=r"(tb) : "r"(sb + GM_TMEMPTR));

    u64 dAhi = mkdesc(sb + GM_AHI);
    u64 dAlo = mkdesc(sb + GM_ALO);
    u64 dBhi = mkdesc(sb + GM_BHI);
    u64 dBlo = mkdesc(sb + GM_BLO);

    uint32_t ph = 0;
    for (int kc = 0; kc < 8; kc++) {
        if (kc) { mbar_wait(sb + GM_MBAR, ph); ph ^= 1; }   // prev chunk MMA done
        int k8 = kc * 8;   // uint4 offset within row
        // A tiles: 1024 uint4 each (hi, lo)
#pragma unroll
        for (int l = 0; l < 4; l++) {
            int idx = tid + l * 256;
            int r = idx >> 3, j = idx & 7;
            uint32_t off = SWZ((uint32_t)(r * 128 + j * 16));
            *(uint4*)(sm + GM_AHI + off) = Ah[r * 64 + k8 + j];
            *(uint4*)(sm + GM_ALO + off) = Al[r * 64 + k8 + j];
        }
        // B tiles: 512 uint4 each
#pragma unroll
        for (int l = 0; l < 2; l++) {
            int idx = tid + l * 256;
            int r = idx >> 3, j = idx & 7;
            uint32_t off = SWZ((uint32_t)(r * 128 + j * 16));
            *(uint4*)(sm + GM_BHI + off) = Bh[r * 64 + k8 + j];
            *(uint4*)(sm + GM_BLO + off) = Bl[r * 64 + k8 + j];
        }
        FPROXY();
        __syncthreads();
        if (wid == 0) {
            if (elect1()) {
#pragma unroll
                for (int ks = 0; ks < 4; ks++)
                    mma_ss(tb, dAhi + ks * 2, dBhi + ks * 2, IDESC, !(kc == 0 && ks == 0));
#pragma unroll
                for (int ks = 0; ks < 4; ks++)
                    mma_ss(tb, dAhi + ks * 2, dBlo + ks * 2, IDESC, 1u);
#pragma unroll
                for (int ks = 0; ks < 4; ks++)
                    mma_ss(tb, dAlo + ks * 2, dBhi + ks * 2, IDESC, 1u);
                tc_commit(sb + GM_MBAR);
            }
        }
    }
    mbar_wait(sb + GM_MBAR, ph); ph ^= 1;

    if (tid < 128) {
        TCF_AFTER();
        uint32_t d[64];
        LDX32(d, tb);
        LDX32(d + 32, tb + 32);
        TC_WAIT_LD();
        int m = mrow0 + tid;
        long long obase = blockIdx.z * sO + (long long)m * ldo + brow0;
        if (Ofp) {
            float bv = bias ? bias[m] : 0.f;
#pragma unroll
            for (int j = 0; j < 16; j++) {
                float4 v = make_float4(__uint_as_float(d[4 * j]) + bv,
                                       __uint_as_float(d[4 * j + 1]) + bv,
                                       __uint_as_float(d[4 * j + 2]) + bv,
                                       __uint_as_float(d[4 * j + 3]) + bv);
                *(float4*)(Ofp + obase + 4 * j) = v;
            }
        } else {
            float sc = (brow0 < qcols) ? scale_q : 1.0f;
            uint32_t whi[32], wlo[32];
#pragma unroll
            for (int j = 0; j < 32; j++) {
                float a = __uint_as_float(d[2 * j]) * sc;
                float b = __uint_as_float(d[2 * j + 1]) * sc;
                u16 ah = f2bf(a), bh = f2bf(b);
                whi[j] = (uint32_t)ah | ((uint32_t)bh << 16);
                u16 al = f2bf(a - bf2f(ah)), bl = f2bf(b - bf2f(bh));
                wlo[j] = (uint32_t)al | ((uint32_t)bl << 16);
            }
#pragma unroll
            for (int j = 0; j < 8; j++) {
                *(uint4*)(Ohi + obase + 8 * j) = *(uint4*)&whi[4 * j];
                *(uint4*)(Olo + obase + 8 * j) = *(uint4*)&wlo[4 * j];
            }
        }
    }
    __syncthreads();
    if (wid == 0) {
        asm volatile("tcgen05.dealloc.cta_group::1.sync.aligned.b32 %0, %1;"
                     :: "r"(tb), "r"(128u));
    }
#else
    // fallback: naive fp32 (compile-only path on non-103a pass)
    int tid = threadIdx.x;
    const u16* Ah = (const u16*)(Ahi + blockIdx.z * sA) + (long long)blockIdx.x * 128 * 512;
    const u16* Al = (const u16*)(Alo + blockIdx.z * sA) + (long long)blockIdx.x * 128 * 512;
    const u16* Bh = (const u16*)(Bhi + blockIdx.z * sB) + (long long)blockIdx.y * 64 * 512;
    const u16* Bl = (const u16*)(Blo + blockIdx.z * sB) + (long long)blockIdx.y * 64 * 512;
    for (int e = tid; e < 128 * 64; e += 256) {
        int r = e >> 6, j = e & 63;
        float s = 0.f;
        for (int k = 0; k < 512; k++)
            s += (bf2f(Ah[r * 512 + k]) + bf2f(Al[r * 512 + k])) *
                 (bf2f(Bh[j * 512 + k]) + bf2f(Bl[j * 512 + k]));
        int m = blockIdx.x * 128 + r;
        long long obase = blockIdx.z * sO + (long long)m * ldo + blockIdx.y * 64 + j;
        if (Ofp) {
            Ofp[obase] = s + (bias ? bias[m] : 0.f);
        } else {
            float sc = (blockIdx.y * 64 < qcols) ? scale_q : 1.0f;
            s *= sc;
            u16 h = f2bf(s);
            Ohi[obase] = h;
            Olo[obase] = f2bf(s - bf2f(h));
        }
    }
#endif
}

// ---------------- 6) attention ---------------------------------------------
#define SM_TMEMPTR 0
#define SM_MBAR 8
#define SM_QHI 1024
#define SM_QLO (SM_QHI + 16384)
#define SM_KHI (SM_QLO + 16384)
#define SM_KLO (SM_KHI + 8192)
#define SM_VHI (SM_KLO + 8192)
#define SM_VLO (SM_VHI + 8192)
#define SM_PHI (SM_VLO + 8192)
#define SM_PLO (SM_PHI + 16384)
#define ATT_SMEM (SM_PLO + 16384)

#define TM_S 0
#define TM_O 64
#define TM_COLS 128

__global__ void __launch_bounds__(256) k_attn(
    const u16* __restrict__ qkthi, const u16* __restrict__ qktlo,
    const u16* __restrict__ vthi,  const u16* __restrict__ vtlo,
    u16* __restrict__ othi, u16* __restrict__ otlo) {
#if HAS_TC
    extern __shared__ char sm[];
    uint32_t sb = smem_u32(sm);
    int tid = threadIdx.x, wid = tid >> 5;
    int n0 = blockIdx.x * 128;
    int h = blockIdx.y, b = blockIdx.z;
    const uint4* qh4 = (const uint4*)qkthi + (long long)b * NPIX * 128;  // 1024/8
    const uint4* ql4 = (const uint4*)qktlo + (long long)b * NPIX * 128;
    const uint4* vh4 = (const uint4*)vthi + ((long long)b * CDIM + h * DH) * 512;
    const uint4* vl4 = (const uint4*)vtlo + ((long long)b * CDIM + h * DH) * 512;

    if (wid == 0) {
        asm volatile("tcgen05.alloc.cta_group::1.sync.aligned.shared::cta.b32 [%0], %1;"
                     :: "r"(sb + SM_TMEMPTR), "r"((uint32_t)TM_COLS) : "memory");
    }
    if (tid == 0) mbar_init1(sb + SM_MBAR);
    __syncthreads();
    uint32_t tb;
    asm volatile("ld.shared.b32 %0, [%1];" : "=r"(tb) : "r"(sb + SM_TMEMPTR));

    // ---- Q tile (128 x 64): direct bf16 copies (pre-scaled, pre-split) ----
#pragma unroll
    for (int l = 0; l < 4; l++) {
        int idx = tid + l * 256;
        int r = idx >> 3, j = idx & 7;
        uint32_t off = SWZ((uint32_t)(r * 128 + j * 16));
        *(uint4*)(sm + SM_QHI + off) = qh4[(long long)(n0 + r) * 128 + h * 8 + j];
        *(uint4*)(sm + SM_QLO + off) = ql4[(long long)(n0 + r) * 128 + h * 8 + j];
    }
    FPROXY();
    __syncthreads();

    u64 aQhi = mkdesc(sb + SM_QHI);
    u64 aQlo = mkdesc(sb + SM_QLO);
    u64 bKhi = mkdesc(sb + SM_KHI);
    u64 bKlo = mkdesc(sb + SM_KLO);
    u64 bVhi = mkdesc(sb + SM_VHI);
    u64 bVlo = mkdesc(sb + SM_VLO);
    u64 aPhi = mkdesc(sb + SM_PHI);
    u64 aPlo = mkdesc(sb + SM_PLO);

    float den = 0.f;
    uint32_t ph = 0;

    for (int t = 0; t < 64; t++) {
        if (t) { mbar_wait(sb + SM_MBAR, ph); ph ^= 1; }   // prev AV done
        int m0 = t * 64;
        // K tile: rows = keys (64), cols 512+h*64 of qkt
#pragma unroll
        for (int l = 0; l < 2; l++) {
            int idx = tid + l * 256;
            int r = idx >> 3, j = idx & 7;
            uint32_t off = SWZ((uint32_t)(r * 128 + j * 16));
            *(uint4*)(sm + SM_KHI + off) = qh4[(long long)(m0 + r) * 128 + 64 + h * 8 + j];
            *(uint4*)(sm + SM_KLO + off) = ql4[(long long)(m0 + r) * 128 + 64 + h * 8 + j];
        }
        // V^T tile: rows = d (64), cols m0..m0+63 of vt
#pragma unroll
        for (int l = 0; l < 2; l++) {
            int idx = tid + l * 256;
            int r = idx >> 3, j = idx & 7;
            uint32_t off = SWZ((uint32_t)(r * 128 + j * 16));
            *(uint4*)(sm + SM_VHI + off) = vh4[(long long)r * 512 + m0 / 8 + j];
            *(uint4*)(sm + SM_VLO + off) = vl4[(long long)r * 512 + m0 / 8 + j];
        }
        FPROXY();
        __syncthreads();

        // ---- S = Q @ K^T ----
        if (wid == 0) {
            if (elect1()) {
#pragma unroll
                for (int ks = 0; ks < 4; ks++)
                    mma_ss(tb + TM_S, aQhi + ks * 2, bKhi + ks * 2, IDESC, ks > 0);
#pragma unroll
                for (int ks = 0; ks < 4; ks++)
                    mma_ss(tb + TM_S, aQhi + ks * 2, bKlo + ks * 2, IDESC, 1u);
#pragma unroll
                for (int ks = 0; ks < 4; ks++)
                    mma_ss(tb + TM_S, aQlo + ks * 2, bKhi + ks * 2, IDESC, 1u);
                tc_commit(sb + SM_MBAR);
            }
        }
        mbar_wait(sb + SM_MBAR, ph); ph ^= 1;

        // ---- softmax: thread owns q-row = tid (warps 0-3) ----
        if (tid < 128) {
            TCF_AFTER();
            uint32_t sr[64];
            LDX32(sr, tb + TM_S);
            LDX32(sr + 32, tb + TM_S + 32);
            TC_WAIT_LD();
            float p[64];
#pragma unroll
            for (int c = 0; c < 64; c++) p[c] = ex2f(__uint_as_float(sr[c]));
            float dsum = 0.f;
#pragma unroll
            for (int c = 0; c < 64; c++) dsum += p[c];
            den += dsum;

            uint32_t rbase = (uint32_t)(tid * 128);
#pragma unroll
            for (int j = 0; j < 32; j++) {
                u16 a = f2bf(p[2 * j]), c = f2bf(p[2 * j + 1]);
                *(uint32_t*)(sm + SM_PHI + SWZ(rbase + j * 4)) =
                    (uint32_t)a | ((uint32_t)c << 16);
            }
#pragma unroll
            for (int j = 0; j < 32; j++) {
                u16 a = f2bf(p[2 * j] - bf2f(f2bf(p[2 * j])));
                u16 c = f2bf(p[2 * j + 1] - bf2f(f2bf(p[2 * j + 1])));
                *(uint32_t*)(sm + SM_PLO + SWZ(rbase + j * 4)) =
                    (uint32_t)a | ((uint32_t)c << 16);
            }
            FPROXY();
        }
        __syncthreads();

        // ---- O += P @ (V^T)^T ----
        if (wid == 0) {
            if (elect1()) {
#pragma unroll
                for (int ks = 0; ks < 4; ks++)
                    mma_ss(tb + TM_O, aPhi + ks * 2, bVhi + ks * 2, IDESC,
                           (t > 0 || ks > 0) ? 1u : 0u);
#pragma unroll
                for (int ks = 0; ks < 4; ks++)
                    mma_ss(tb + TM_O, aPhi + ks * 2, bVlo + ks * 2, IDESC, 1u);
#pragma unroll
                for (int ks = 0; ks < 4; ks++)
                    mma_ss(tb + TM_O, aPlo + ks * 2, bVhi + ks * 2, IDESC, 1u);
                tc_commit(sb + SM_MBAR);
            }
        }
    }
    mbar_wait(sb + SM_MBAR, ph); ph ^= 1;

    // ---- epilogue: (O / den) -> bf16 hi/lo ot[n][512] ----
    if (tid < 128) {
        TCF_AFTER();
        uint32_t orr[64];
        LDX32(orr, tb + TM_O);
        LDX32(orr + 32, tb + TM_O + 32);
        TC_WAIT_LD();
        float inv = 1.0f / den;
        long long obase = ((long long)b * NPIX + n0 + tid) * CDIM + h * DH;
        uint32_t whi[32], wlo[32];
#pragma unroll
        for (int j = 0; j < 32; j++) {
            float a = __uint_as_float(orr[2 * j]) * inv;
            float c = __uint_as_float(orr[2 * j + 1]) * inv;
            u16 ah = f2bf(a), ch = f2bf(c);
            whi[j] = (uint32_t)ah | ((uint32_t)ch << 16);
            u16 al = f2bf(a - bf2f(ah)), cl = f2bf(c - bf2f(ch));
            wlo[j] = (uint32_t)al | ((uint32_t)cl << 16);
        }
#pragma unroll
        for (int j = 0; j < 8; j++) {
            *(uint4*)(othi + obase + 8 * j) = *(uint4*)&whi[4 * j];
            *(uint4*)(otlo + obase + 8 * j) = *(uint4*)&wlo[4 * j];
        }
    }
    __syncthreads();
    if (wid == 0) {
        asm volatile("tcgen05.dealloc.cta_group::1.sync.aligned.b32 %0, %1;"
                     :: "r"(tb), "r"((uint32_t)TM_COLS));
    }
#else
    // fallback: naive (compile-only path)
    int tid = threadIdx.x;
    if (tid >= 128) return;
    int n0 = blockIdx.x * 128;
    int h = blockIdx.y, b = blockIdx.z;
    long long qb = (long long)b * NPIX * QKD;
    int r = n0 + tid;
    float q[64], o[64], den = 0.f;
#pragma unroll
    for (int d = 0; d < 64; d++) {
        q[d] = bf2f(qkthi[qb + (long long)r * QKD + h * 64 + d]) +
               bf2f(qktlo[qb + (long long)r * QKD + h * 64 + d]);
        o[d] = 0.f;
    }
    for (int key = 0; key < NPIX; key++) {
        float s = 0.f;
        for (int d = 0; d < 64; d++)
            s += q[d] * (bf2f(qkthi[qb + (long long)key * QKD + 512 + h * 64 + d]) +
                         bf2f(qktlo[qb + (long long)key * QKD + 512 + h * 64 + d]));
        float p = ex2f(s);
        den += p;
        for (int d = 0; d < 64; d++) {
            long long vi = ((long long)b * CDIM + h * 64 + d) * NPIX + key;
            o[d] += p * (bf2f(vthi[vi]) + bf2f(vtlo[vi]));
        }
    }
    long long ob = ((long long)b * NPIX + r) * CDIM + h * 64;
    for (int d = 0; d < 64; d++) {
        float v = o[d] / den;
        u16 hh = f2bf(v);
        othi[ob + d] = hh;
        otlo[ob + d] = f2bf(v - bf2f(hh));
    }
#endif
}

// ---------------------------------------------------------------------------
extern "C" void kernel_launch(void* const* d_in, const int* in_sizes, int n_in,
                              void* d_out, int out_size) {
    const float* x      = (const float*)d_in[0];
    const float* dw_w   = (const float*)d_in[1];
    const float* qkv_w  = (const float*)d_in[2];
    const float* proj_w = (const float*)d_in[3];
    const float* proj_b = (const float*)d_in[4];
    float* out = (float*)d_out;

    float* py;
    u16 *pythi, *pytlo, *pwhi, *pwlo, *ppwhi, *ppwlo;
    u16 *pqkthi, *pqktlo, *pvthi, *pvtlo, *pothi, *potlo;
    cudaGetSymbolAddress((void**)&py,     g_y);
    cudaGetSymbolAddress((void**)&pythi,  g_ythi);
    cudaGetSymbolAddress((void**)&pytlo,  g_ytlo);
    cudaGetSymbolAddress((void**)&pwhi,   g_whi);
    cudaGetSymbolAddress((void**)&pwlo,   g_wlo);
    cudaGetSymbolAddress((void**)&ppwhi,  g_pwhi);
    cudaGetSymbolAddress((void**)&ppwlo,  g_pwlo);
    cudaGetSymbolAddress((void**)&pqkthi, g_qkthi);
    cudaGetSymbolAddress((void**)&pqktlo, g_qktlo);
    cudaGetSymbolAddress((void**)&pvthi,  g_vthi);
    cudaGetSymbolAddress((void**)&pvtlo,  g_vtlo);
    cudaGetSymbolAddress((void**)&pothi,  g_othi);
    cudaGetSymbolAddress((void**)&potlo,  g_otlo);

    cudaFuncSetAttribute(k_attn, cudaFuncAttributeMaxDynamicSharedMemorySize, ATT_SMEM);
    cudaFuncSetAttribute(k_gemm_tc, cudaFuncAttributeMaxDynamicSharedMemorySize, GM_SMEM);

    // 1) depthwise conv
    k_dwconv<<<(TOTAL + 255) / 256, 256>>>(x, dw_w, py);

    // 2) weight conversions
    k_cvt<<<(3 * CDIM * CDIM + 255) / 256, 256>>>(qkv_w, pwhi, pwlo, 3 * CDIM * CDIM);
    k_cvt<<<(CDIM * CDIM + 255) / 256, 256>>>(proj_w, ppwhi, ppwlo, CDIM * CDIM);

    // 3) y -> yT bf16 hi/lo
    {
        dim3 grid(NPIX / 32, CDIM / 32, BATCH);
        k_t2bf<<<grid, dim3(32, 8)>>>(py, pythi, pytlo);
    }

    long long sYT = (long long)NPIX * CDIM / 8;   // uint4 stride per batch

    // 4) qk GEMM: qkt[n][1024], q cols scaled
    {
        dim3 grid(NPIX / 128, QKD / 64, BATCH);
        k_gemm_tc<<<grid, 256, GM_SMEM>>>(
            (const uint4*)pythi, (const uint4*)pytlo, sYT,
            (const uint4*)pwhi, (const uint4*)pwlo, 0,
            pqkthi, pqktlo, nullptr, nullptr,
            (long long)NPIX * QKD, QKD, ATT_SCALE_L2E, 512);
    }

    // 5) V GEMM: vt[c][n]
    {
        dim3 grid(CDIM / 128, NPIX / 64, BATCH);
        k_gemm_tc<<<grid, 256, GM_SMEM>>>(
            (const uint4*)(pwhi + 1024 * CDIM), (const uint4*)(pwlo + 1024 * CDIM), 0,
            (const uint4*)pythi, (const uint4*)pytlo, sYT,
            pvthi, pvtlo, nullptr, nullptr,
            (long long)CDIM * NPIX, NPIX, 1.0f, 0);
    }

    // 6) attention -> ot[n][512] bf16 hi/lo
    {
        dim3 grid(NPIX / 128, HEADS, BATCH);
        k_attn<<<grid, 256, ATT_SMEM>>>(pqkthi, pqktlo, pvthi, pvtlo, pothi, potlo);
    }

    // 7) proj GEMM + bias -> out[c][n] fp32
    {
        dim3 grid(CDIM / 128, NPIX / 64, BATCH);
        k_gemm_tc<<<grid, 256, GM_SMEM>>>(
            (const uint4*)ppwhi, (const uint4*)ppwlo, 0,
            (const uint4*)pothi, (const uint4*)potlo, sYT,
            nullptr, nullptr, out, proj_b,
            (long long)CDIM * NPIX, NPIX, 1.0f, 0);
    }
}